// round 15
// baseline (speedup 1.0000x reference)
#include <cuda_runtime.h>
#include <cuda_bf16.h>
#include <cuda_fp16.h>
#include <cstdint>

#define NN 50000
#define NE 1600000
#define D 128
#define LL 4
#define BN_EPS 1e-5f
#define SCAN_BLKS 196

// ---------------- device scratch ----------------
__device__ float g_H [NN * D];
__device__ float g_X [NN * D];
__device__ float g_Y1[NN * D];
__device__ float g_Y2[NN * D];
__device__ __half g_Hh[NN * D];     // fp16 mirror of H for the gather

__device__ int   g_deg   [NN];
__device__ int   g_rowptr[NN + 1];
__device__ int   g_cursor[NN];
__device__ int   g_col   [NE];
__device__ int   g_bsum  [256];

// per-layer stats: [layer][stage 0..2][sum|sumsq][D]
__device__ float g_statsAll[LL * 3 * 2 * D];

// pre-transposed fp16 weights [mat][n][k]: 0=embed, 1..4=W1, 5..8=W2
__device__ __half g_Wf[9 * 16384];

// ---------------- helpers ----------------
__device__ __forceinline__ uint32_t pack_f16_hi(float a, float b, float& ra, float& rb) {
    __half ha = __float2half_rn(a);
    __half hb = __float2half_rn(b);
    ra = a - __half2float(ha);
    rb = b - __half2float(hb);
    return (uint32_t)__half_as_ushort(ha) | ((uint32_t)__half_as_ushort(hb) << 16);
}
__device__ __forceinline__ uint32_t pack_f16(float a, float b) {
    return (uint32_t)__half_as_ushort(__float2half_rn(a))
         | ((uint32_t)__half_as_ushort(__float2half_rn(b)) << 16);
}
#define MMA16816(c, a, b)                                                      \
    asm volatile(                                                              \
        "mma.sync.aligned.m16n8k16.row.col.f32.f16.f16.f32 "                   \
        "{%0,%1,%2,%3}, {%4,%5,%6,%7}, {%8,%9}, {%0,%1,%2,%3};"                \
        : "+f"((c)[0]), "+f"((c)[1]), "+f"((c)[2]), "+f"((c)[3])               \
        : "r"((a)[0]), "r"((a)[1]), "r"((a)[2]), "r"((a)[3]),                  \
          "r"((b)[0]), "r"((b)[1]))
#define LDSM_X4(r0, r1, r2, r3, addr)                                          \
    asm volatile(                                                              \
        "ldmatrix.sync.aligned.m8n8.x4.shared.b16 {%0,%1,%2,%3}, [%4];"        \
        : "=r"(r0), "=r"(r1), "=r"(r2), "=r"(r3) : "r"(addr))

// ---------------- upfront zero ----------------
__global__ void k_zero_all() {
    int i = blockIdx.x * blockDim.x + threadIdx.x;
    if (i < NN) g_deg[i] = 0;
    if (i < LL * 3 * 2 * D) g_statsAll[i] = 0.f;
}

// ---------------- weight prep: fp32 W[k][n] -> fp16 at [n][k] ----------------
__global__ void k_prepW(const float* __restrict__ We, const float* __restrict__ W1,
                        const float* __restrict__ W2) {
    int mat = blockIdx.y;
    const float* src = (mat == 0) ? We : (mat < 5) ? (W1 + (mat - 1) * D * D)
                                                   : (W2 + (mat - 5) * D * D);
    int idx = blockIdx.x * 256 + threadIdx.x;   // over [k][n]
    int k = idx >> 7, n = idx & 127;
    g_Wf[mat * 16384 + n * 128 + k] = __float2half_rn(src[idx]);
}

// ---------------- CSR build ----------------
__global__ void k_hist(const int* __restrict__ dst) {
    int e = blockIdx.x * blockDim.x + threadIdx.x;
    if (e < NE) atomicAdd(&g_deg[dst[e]], 1);
}

__global__ void __launch_bounds__(256) k_scan1() {
    __shared__ int sh[256];
    int t = threadIdx.x;
    int i = blockIdx.x * 256 + t;
    int d = (i < NN) ? g_deg[i] : 0;
    sh[t] = d;
    __syncthreads();
#pragma unroll
    for (int off = 1; off < 256; off <<= 1) {
        int v = (t >= off) ? sh[t - off] : 0;
        __syncthreads();
        sh[t] += v;
        __syncthreads();
    }
    if (i < NN) g_rowptr[i] = sh[t] - d;
    if (t == 255) g_bsum[blockIdx.x] = sh[255];
}

// merged scan2+scan3
__global__ void __launch_bounds__(256) k_scan23() {
    __shared__ int sh[256];
    int t = threadIdx.x;
    int v0 = (t < SCAN_BLKS) ? g_bsum[t] : 0;
    sh[t] = v0;
    __syncthreads();
#pragma unroll
    for (int off = 1; off < 256; off <<= 1) {
        int v = (t >= off) ? sh[t - off] : 0;
        __syncthreads();
        sh[t] += v;
        __syncthreads();
    }
    int excl = sh[blockIdx.x] - g_bsum[blockIdx.x];
    int i = blockIdx.x * 256 + t;
    if (i < NN) {
        int v = g_rowptr[i] + excl;
        g_rowptr[i] = v;
        g_cursor[i] = v;
    }
    if (i == 0) g_rowptr[NN] = NE;
}

__global__ void k_fill(const int* __restrict__ src, const int* __restrict__ dst) {
    int e = blockIdx.x * blockDim.x + threadIdx.x;
    if (e < NE) {
        int p = atomicAdd(&g_cursor[dst[e]], 1);
        g_col[p] = src[e];
    }
}

// ---------------- aggregation: fp32 self term + fp16 neighbor gather, MLP=8 ----------------
__global__ void k_agg(const float* __restrict__ eps, int layer) {
    int gw   = (blockIdx.x * blockDim.x + threadIdx.x) >> 5;
    int lane = threadIdx.x & 31;
    if (gw >= NN) return;
    float sc = 1.0f + eps[layer];
    float4 a = ((const float4*)g_H)[gw * 32 + lane];
    float4 acc;
    acc.x = sc * a.x; acc.y = sc * a.y; acc.z = sc * a.z; acc.w = sc * a.w;
    const uint2* __restrict__ Hh2 = (const uint2*)g_Hh;
    int e = g_rowptr[gw], eE = g_rowptr[gw + 1];
    for (; e + 8 <= eE; e += 8) {
        int s0 = g_col[e + 0], s1 = g_col[e + 1], s2 = g_col[e + 2], s3 = g_col[e + 3];
        int s4 = g_col[e + 4], s5 = g_col[e + 5], s6 = g_col[e + 6], s7 = g_col[e + 7];
        uint2 v0 = Hh2[s0 * 32 + lane];
        uint2 v1 = Hh2[s1 * 32 + lane];
        uint2 v2 = Hh2[s2 * 32 + lane];
        uint2 v3 = Hh2[s3 * 32 + lane];
        uint2 v4 = Hh2[s4 * 32 + lane];
        uint2 v5 = Hh2[s5 * 32 + lane];
        uint2 v6 = Hh2[s6 * 32 + lane];
        uint2 v7 = Hh2[s7 * 32 + lane];
        float2 a0 = __half22float2(*(const __half2*)&v0.x), b0 = __half22float2(*(const __half2*)&v0.y);
        float2 a1 = __half22float2(*(const __half2*)&v1.x), b1 = __half22float2(*(const __half2*)&v1.y);
        float2 a2 = __half22float2(*(const __half2*)&v2.x), b2 = __half22float2(*(const __half2*)&v2.y);
        float2 a3 = __half22float2(*(const __half2*)&v3.x), b3 = __half22float2(*(const __half2*)&v3.y);
        float2 a4 = __half22float2(*(const __half2*)&v4.x), b4 = __half22float2(*(const __half2*)&v4.y);
        float2 a5 = __half22float2(*(const __half2*)&v5.x), b5 = __half22float2(*(const __half2*)&v5.y);
        float2 a6 = __half22float2(*(const __half2*)&v6.x), b6 = __half22float2(*(const __half2*)&v6.y);
        float2 a7 = __half22float2(*(const __half2*)&v7.x), b7 = __half22float2(*(const __half2*)&v7.y);
        acc.x += ((a0.x + a1.x) + (a2.x + a3.x)) + ((a4.x + a5.x) + (a6.x + a7.x));
        acc.y += ((a0.y + a1.y) + (a2.y + a3.y)) + ((a4.y + a5.y) + (a6.y + a7.y));
        acc.z += ((b0.x + b1.x) + (b2.x + b3.x)) + ((b4.x + b5.x) + (b6.x + b7.x));
        acc.w += ((b0.y + b1.y) + (b2.y + b3.y)) + ((b4.y + b5.y) + (b6.y + b7.y));
    }
    for (; e + 4 <= eE; e += 4) {
        int s0 = g_col[e + 0], s1 = g_col[e + 1], s2 = g_col[e + 2], s3 = g_col[e + 3];
        uint2 v0 = Hh2[s0 * 32 + lane];
        uint2 v1 = Hh2[s1 * 32 + lane];
        uint2 v2 = Hh2[s2 * 32 + lane];
        uint2 v3 = Hh2[s3 * 32 + lane];
        float2 a0 = __half22float2(*(const __half2*)&v0.x), b0 = __half22float2(*(const __half2*)&v0.y);
        float2 a1 = __half22float2(*(const __half2*)&v1.x), b1 = __half22float2(*(const __half2*)&v1.y);
        float2 a2 = __half22float2(*(const __half2*)&v2.x), b2 = __half22float2(*(const __half2*)&v2.y);
        float2 a3 = __half22float2(*(const __half2*)&v3.x), b3 = __half22float2(*(const __half2*)&v3.y);
        acc.x += (a0.x + a1.x) + (a2.x + a3.x);
        acc.y += (a0.y + a1.y) + (a2.y + a3.y);
        acc.z += (b0.x + b1.x) + (b2.x + b3.x);
        acc.w += (b0.y + b1.y) + (b2.y + b3.y);
    }
    for (; e < eE; e++) {
        uint2 v = Hh2[g_col[e] * 32 + lane];
        float2 aa = __half22float2(*(const __half2*)&v.x);
        float2 bb = __half22float2(*(const __half2*)&v.y);
        acc.x += aa.x; acc.y += aa.y; acc.z += bb.x; acc.w += bb.y;
    }
    ((float4*)g_X)[gw * 32 + lane] = acc;
}

// ---------------- HMMA GEMM: C[M,128] = A[M,128] @ W[128,128] + bias ----------------
// fp16 2-term split: A = Ah + Al, W single fp16. D = Ah@W + Al@W.
// BM=64, BN=128. A loaded ONCE (MLP=8 prologue) into read-only smem [8][64][16];
// W register-staged double-buffer [2][128][24] (LD t+1 -> MMA t -> ST -> sync).
#define ASTR 16
#define WSTRD 24
#define GBM 64

template <bool NORM, bool STATS, bool MIRROR>
__global__ void __launch_bounds__(256, 3) k_hgemm(
    const float* __restrict__ Ain,
    const __half* __restrict__ Wf,
    const float* __restrict__ bias,
    const float* __restrict__ gam, const float* __restrict__ bet,
    const float* __restrict__ statIn, float* __restrict__ statOut,
    float* __restrict__ C)
{
    __shared__ __align__(16) unsigned char smraw[47104];
    __half* AhS = (__half*)smraw;                          // [8][64][ASTR] = 16384B
    __half* AlS = AhS + 8 * 64 * ASTR;                     // 16384B
    __half* WS  = AlS + 8 * 64 * ASTR;                     // [2][128][WSTRD] = 12288B
    float* nrm = (float*)(smraw + 45056);                  // 4 x 128 = 2048B
    float* red = (float*)smraw;                            // epilogue overlay [16][128]

    const int tid  = threadIdx.x;
    const int lane = tid & 31;
    const int w    = tid >> 5;
    const int wm   = w >> 2;       // 0..1 (32-row block)
    const int wn   = w & 3;        // 0..3 (32-col block)
    const int row0 = blockIdx.x * GBM;
    const int arow = tid >> 2;     // 0..63  (A row this thread loads)
    const int aq   = tid & 3;      // k-quarter (32 cols) this thread handles
    const int wrow = tid >> 1;     // 0..127 (W load row)
    const int wk   = (tid & 1) * 8;// W k-offset within 16

    if (NORM) {
        if (tid < 128) {
            float s = statIn[tid], q = statIn[128 + tid];
            float mu  = s * (1.0f / NN);
            float var = q * (1.0f / NN) - mu * mu;
            nrm[tid]       = mu;
            nrm[128 + tid] = rsqrtf(var + BN_EPS);
            nrm[256 + tid] = gam[tid];
            nrm[384 + tid] = bet[tid];
        }
        __syncthreads();
    }

    const __half* wSrc = Wf + wrow * 128 + wk;
    uint4 vw;

    // ---- W stage 0 load (in flight during A prologue) ----
    vw = *(const uint4*)(wSrc);

    // ---- A prologue: 32 values per thread at MLP=8, BN+relu, fp16 split, all stages ----
    {
        int row = row0 + arow;
        const float4* ap = (const float4*)(Ain + (size_t)row * 128 + aq * 32);
        float v[32];
        if (row < NN) {
            float4 f0 = ap[0], f1 = ap[1], f2 = ap[2], f3 = ap[3];
            float4 f4 = ap[4], f5 = ap[5], f6 = ap[6], f7 = ap[7];
            v[0]=f0.x; v[1]=f0.y; v[2]=f0.z; v[3]=f0.w;
            v[4]=f1.x; v[5]=f1.y; v[6]=f1.z; v[7]=f1.w;
            v[8]=f2.x; v[9]=f2.y; v[10]=f2.z; v[11]=f2.w;
            v[12]=f3.x; v[13]=f3.y; v[14]=f3.z; v[15]=f3.w;
            v[16]=f4.x; v[17]=f4.y; v[18]=f4.z; v[19]=f4.w;
            v[20]=f5.x; v[21]=f5.y; v[22]=f5.z; v[23]=f5.w;
            v[24]=f6.x; v[25]=f6.y; v[26]=f6.z; v[27]=f6.w;
            v[28]=f7.x; v[29]=f7.y; v[30]=f7.z; v[31]=f7.w;
        } else {
#pragma unroll
            for (int j = 0; j < 32; j++) v[j] = 0.f;
        }
        if (NORM) {
#pragma unroll
            for (int j = 0; j < 32; j++) {
                int cc = aq * 32 + j;
                v[j] = fmaxf(fmaf(nrm[256 + cc] * (v[j] - nrm[cc]),
                                  nrm[128 + cc], nrm[384 + cc]), 0.f);
            }
        }
        uint32_t hw[16], lw[16];
#pragma unroll
        for (int j = 0; j < 16; j++) {
            float r0, r1;
            hw[j] = pack_f16_hi(v[2 * j], v[2 * j + 1], r0, r1);
            lw[j] = pack_f16(r0, r1);
        }
        // stages 2*aq and 2*aq+1 (each 16 k = 8 uint32 = 2 uint4)
        __half* d0h = &AhS[((2 * aq) * 64 + arow) * ASTR];
        __half* d1h = &AhS[((2 * aq + 1) * 64 + arow) * ASTR];
        __half* d0l = &AlS[((2 * aq) * 64 + arow) * ASTR];
        __half* d1l = &AlS[((2 * aq + 1) * 64 + arow) * ASTR];
        *(uint4*)(d0h)     = make_uint4(hw[0], hw[1], hw[2], hw[3]);
        *(uint4*)(d0h + 8) = make_uint4(hw[4], hw[5], hw[6], hw[7]);
        *(uint4*)(d1h)     = make_uint4(hw[8], hw[9], hw[10], hw[11]);
        *(uint4*)(d1h + 8) = make_uint4(hw[12], hw[13], hw[14], hw[15]);
        *(uint4*)(d0l)     = make_uint4(lw[0], lw[1], lw[2], lw[3]);
        *(uint4*)(d0l + 8) = make_uint4(lw[4], lw[5], lw[6], lw[7]);
        *(uint4*)(d1l)     = make_uint4(lw[8], lw[9], lw[10], lw[11]);
        *(uint4*)(d1l + 8) = make_uint4(lw[12], lw[13], lw[14], lw[15]);
    }
    // store W stage 0
    *(uint4*)&WS[0 * 128 * WSTRD + wrow * WSTRD + wk] = vw;
    __syncthreads();

    // ldmatrix per-lane offsets
    const int a_row = wm * 32 + (lane & 15);                       // + m*16
    const int a_ko  = (lane >> 4) << 3;                            // 0 or 8
    const int b_row = wn * 32 + (lane & 7) + ((lane >> 4) << 3);   // + g*16
    const int b_ko  = ((lane >> 3) & 1) << 3;                      // 0 or 8

    float acc[2][4][4];
#pragma unroll
    for (int m = 0; m < 2; m++)
#pragma unroll
        for (int n = 0; n < 4; n++)
#pragma unroll
            for (int j = 0; j < 4; j++) acc[m][n][j] = 0.f;

#pragma unroll
    for (int t = 0; t < 8; t++) {
        const int buf = t & 1;
        if (t < 7) vw = *(const uint4*)(wSrc + (t + 1) * 16);

        uint32_t ah[2][4], al[2][4];
#pragma unroll
        for (int m = 0; m < 2; m++) {
            uint32_t pa = (uint32_t)__cvta_generic_to_shared(
                &AhS[(t * 64 + a_row + m * 16) * ASTR + a_ko]);
            LDSM_X4(ah[m][0], ah[m][1], ah[m][2], ah[m][3], pa);
            uint32_t pl = (uint32_t)__cvta_generic_to_shared(
                &AlS[(t * 64 + a_row + m * 16) * ASTR + a_ko]);
            LDSM_X4(al[m][0], al[m][1], al[m][2], al[m][3], pl);
        }
        uint32_t bh[4][2];
#pragma unroll
        for (int g = 0; g < 2; g++) {
            uint32_t pb = (uint32_t)__cvta_generic_to_shared(
                &WS[buf * 128 * WSTRD + (b_row + g * 16) * WSTRD + b_ko]);
            LDSM_X4(bh[2 * g][0], bh[2 * g][1], bh[2 * g + 1][0], bh[2 * g + 1][1], pb);
        }
#pragma unroll
        for (int m = 0; m < 2; m++)
#pragma unroll
            for (int n = 0; n < 4; n++) {
                MMA16816(acc[m][n], ah[m], bh[n]);
                MMA16816(acc[m][n], al[m], bh[n]);
            }
        if (t < 7)
            *(uint4*)&WS[(buf ^ 1) * 128 * WSTRD + wrow * WSTRD + wk] = vw;
        __syncthreads();
    }

    // ---- epilogue: bias + store + optional column stats ----
    float ps[4][2], pq[4][2];
    if (STATS) {
#pragma unroll
        for (int n = 0; n < 4; n++) { ps[n][0] = ps[n][1] = 0.f; pq[n][0] = pq[n][1] = 0.f; }
    }
#pragma unroll
    for (int m = 0; m < 2; m++) {
        int ra = row0 + wm * 32 + m * 16 + (lane >> 2);
        int rb = ra + 8;
        bool vva = ra < NN, vvb = rb < NN;
#pragma unroll
        for (int n = 0; n < 4; n++) {
            int col = wn * 32 + n * 8 + ((lane & 3) << 1);
            float2 b2 = *(const float2*)&bias[col];
            float o0 = acc[m][n][0] + b2.x, o1 = acc[m][n][1] + b2.y;
            float o2 = acc[m][n][2] + b2.x, o3 = acc[m][n][3] + b2.y;
            if (vva) {
                *(float2*)&C[ra * 128 + col] = make_float2(o0, o1);
                if (MIRROR) {
                    __half2 hh = __floats2half2_rn(o0, o1);
                    *(__half2*)&g_Hh[ra * 128 + col] = hh;
                }
            }
            if (vvb) {
                *(float2*)&C[rb * 128 + col] = make_float2(o2, o3);
                if (MIRROR) {
                    __half2 hh = __floats2half2_rn(o2, o3);
                    *(__half2*)&g_Hh[rb * 128 + col] = hh;
                }
            }
            if (STATS) {
                if (vva) { ps[n][0] += o0; pq[n][0] += o0 * o0; ps[n][1] += o1; pq[n][1] += o1 * o1; }
                if (vvb) { ps[n][0] += o2; pq[n][0] += o2 * o2; ps[n][1] += o3; pq[n][1] += o3 * o3; }
            }
        }
    }
    if (STATS) {
        const int contrib = wm * 8 + (lane >> 2);   // 0..15
        __syncthreads();
#pragma unroll
        for (int n = 0; n < 4; n++) {
            int col = wn * 32 + n * 8 + ((lane & 3) << 1);
            red[contrib * 128 + col]     = ps[n][0];
            red[contrib * 128 + col + 1] = ps[n][1];
        }
        __syncthreads();
        if (tid < 128) {
            float s = 0.f;
#pragma unroll
            for (int g = 0; g < 16; g++) s += red[g * 128 + tid];
            atomicAdd(&statOut[tid], s);
        }
        __syncthreads();
#pragma unroll
        for (int n = 0; n < 4; n++) {
            int col = wn * 32 + n * 8 + ((lane & 3) << 1);
            red[contrib * 128 + col]     = pq[n][0];
            red[contrib * 128 + col + 1] = pq[n][1];
        }
        __syncthreads();
        if (tid < 128) {
            float s = 0.f;
#pragma unroll
            for (int g = 0; g < 16; g++) s += red[g * 128 + tid];
            atomicAdd(&statOut[128 + tid], s);
        }
    }
}

// ---------------- stats of A = relu(BN(Y2; st1)) -> statOut ----------------
#define SROWS 256
__global__ void __launch_bounds__(256) k_bnrelu_stats(
    const float* __restrict__ gam, const float* __restrict__ bet,
    const float* __restrict__ statIn, float* __restrict__ statOut)
{
    int tid = threadIdx.x;
    int c4  = tid & 31;
    int rg  = tid >> 5;
    int cc  = c4 * 4;
    float4 s4 = *(const float4*)&statIn[cc];
    float4 q4 = *(const float4*)&statIn[128 + cc];
    float4 m4, r4;
    m4.x = s4.x * (1.0f / NN); r4.x = rsqrtf(q4.x * (1.0f / NN) - m4.x * m4.x + BN_EPS);
    m4.y = s4.y * (1.0f / NN); r4.y = rsqrtf(q4.y * (1.0f / NN) - m4.y * m4.y + BN_EPS);
    m4.z = s4.z * (1.0f / NN); r4.z = rsqrtf(q4.z * (1.0f / NN) - m4.z * m4.z + BN_EPS);
    m4.w = s4.w * (1.0f / NN); r4.w = rsqrtf(q4.w * (1.0f / NN) - m4.w * m4.w + BN_EPS);
    float4 g4 = *(const float4*)&gam[cc];
    float4 b4 = *(const float4*)&bet[cc];
    float s[4] = {0.f, 0.f, 0.f, 0.f}, q[4] = {0.f, 0.f, 0.f, 0.f};
    int rEnd = min(blockIdx.x * SROWS + SROWS, NN);
    for (int r = blockIdx.x * SROWS + rg; r < rEnd; r += 8) {
        float4 v = *(const float4*)&g_Y2[r * 128 + cc];
        float4 a;
        a.x = fmaxf(fmaf(g4.x * (v.x - m4.x), r4.x, b4.x), 0.f);
        a.y = fmaxf(fmaf(g4.y * (v.y - m4.y), r4.y, b4.y), 0.f);
        a.z = fmaxf(fmaf(g4.z * (v.z - m4.z), r4.z, b4.z), 0.f);
        a.w = fmaxf(fmaf(g4.w * (v.w - m4.w), r4.w, b4.w), 0.f);
        s[0] += a.x; q[0] += a.x * a.x;
        s[1] += a.y; q[1] += a.y * a.y;
        s[2] += a.z; q[2] += a.z * a.z;
        s[3] += a.w; q[3] += a.w * a.w;
    }
    __shared__ float shs[8][128];
    __shared__ float shq[8][128];
#pragma unroll
    for (int j = 0; j < 4; j++) { shs[rg][cc + j] = s[j]; shq[rg][cc + j] = q[j]; }
    __syncthreads();
    if (tid < 128) {
        float ts = 0.f, tq = 0.f;
#pragma unroll
        for (int g = 0; g < 8; g++) { ts += shs[g][tid]; tq += shq[g][tid]; }
        atomicAdd(&statOut[tid],       ts);
        atomicAdd(&statOut[128 + tid], tq);
    }
}

// ---------------- Hout = H + relu(BN(relu(BN(Y2; st1)); st2)); optional fp16 mirror ----------------
__global__ void __launch_bounds__(256) k_residual(
    const float* __restrict__ ga, const float* __restrict__ ba,
    const float* __restrict__ gl, const float* __restrict__ bl,
    const float* __restrict__ st1, const float* __restrict__ st2,
    float* __restrict__ out, int writeH)
{
    int i4 = blockIdx.x * blockDim.x + threadIdx.x;
    if (i4 >= NN * 32) return;
    int cc = (i4 & 31) * 4;
    float4 s4 = *(const float4*)&st1[cc];
    float4 q4 = *(const float4*)&st1[128 + cc];
    float4 m1, r1;
    m1.x = s4.x * (1.0f / NN); r1.x = rsqrtf(q4.x * (1.0f / NN) - m1.x * m1.x + BN_EPS);
    m1.y = s4.y * (1.0f / NN); r1.y = rsqrtf(q4.y * (1.0f / NN) - m1.y * m1.y + BN_EPS);
    m1.z = s4.z * (1.0f / NN); r1.z = rsqrtf(q4.z * (1.0f / NN) - m1.z * m1.z + BN_EPS);
    m1.w = s4.w * (1.0f / NN); r1.w = rsqrtf(q4.w * (1.0f / NN) - m1.w * m1.w + BN_EPS);
    float4 ga4 = *(const float4*)&ga[cc];
    float4 ba4 = *(const float4*)&ba[cc];
    float4 t4 = *(const float4*)&st2[cc];
    float4 u4 = *(const float4*)&st2[128 + cc];
    float4 m2, r2;
    m2.x = t4.x * (1.0f / NN); r2.x = rsqrtf(u4.x * (1.0f / NN) - m2.x * m2.x + BN_EPS);
    m2.y = t4.y * (1.0f / NN); r2.y = rsqrtf(u4.y * (1.0f / NN) - m2.y * m2.y + BN_EPS);
    m2.z = t4.z * (1.0f / NN); r2.z = rsqrtf(u4.z * (1.0f / NN) - m2.z * m2.z + BN_EPS);
    m2.w = t4.w * (1.0f / NN); r2.w = rsqrtf(u4.w * (1.0f / NN) - m2.w * m2.w + BN_EPS);
    float4 gl4 = *(const float4*)&gl[cc];
    float4 bl4 = *(const float4*)&bl[cc];

    float4 v = ((const float4*)g_Y2)[i4];
    float4 h = ((const float4*)g_H)[i4];
    float4 a, o;
    a.x = fmaxf(fmaf(ga4.x * (v.x - m1.x), r1.x, ba4.x), 0.f);
    a.y = fmaxf(fmaf(ga4.y * (v.y - m1.y), r1.y, ba4.y), 0.f);
    a.z = fmaxf(fmaf(ga4.z * (v.z - m1.z), r1.z, ba4.z), 0.f);
    a.w = fmaxf(fmaf(ga4.w * (v.w - m1.w), r1.w, ba4.w), 0.f);
    o.x = h.x + fmaxf(fmaf(gl4.x * (a.x - m2.x), r2.x, bl4.x), 0.f);
    o.y = h.y + fmaxf(fmaf(gl4.y * (a.y - m2.y), r2.y, bl4.y), 0.f);
    o.z = h.z + fmaxf(fmaf(gl4.z * (a.z - m2.z), r2.z, bl4.z), 0.f);
    o.w = h.w + fmaxf(fmaf(gl4.w * (a.w - m2.w), r2.w, bl4.w), 0.f);
    ((float4*)out)[i4] = o;
    if (writeH) {
        __half2 h01 = __floats2half2_rn(o.x, o.y);
        __half2 h23 = __floats2half2_rn(o.z, o.w);
        uint2 u;
        u.x = *(uint32_t*)&h01;
        u.y = *(uint32_t*)&h23;
        ((uint2*)g_Hh)[i4] = u;
    }
}

// ---------------- launcher ----------------
extern "C" void kernel_launch(void* const* d_in, const int* in_sizes, int n_in,
                              void* d_out, int out_size)
{
    const float* h       = (const float*)d_in[0];
    const int*   src     = (const int*)  d_in[1];
    const int*   dst     = (const int*)  d_in[2];
    const float* W_embed = (const float*)d_in[3];
    const float* b_embed = (const float*)d_in[4];
    const float* eps     = (const float*)d_in[5];
    const float* W1      = (const float*)d_in[6];
    const float* b1      = (const float*)d_in[7];
    const float* g1      = (const float*)d_in[8];
    const float* be1     = (const float*)d_in[9];
    const float* W2      = (const float*)d_in[10];
    const float* b2      = (const float*)d_in[11];
    const float* ga      = (const float*)d_in[12];
    const float* ba      = (const float*)d_in[13];
    const float* gl      = (const float*)d_in[14];
    const float* bl      = (const float*)d_in[15];

    float *pH, *pX, *pY1, *pY2, *pStats;
    cudaGetSymbolAddress((void**)&pH,     g_H);
    cudaGetSymbolAddress((void**)&pX,     g_X);
    cudaGetSymbolAddress((void**)&pY1,    g_Y1);
    cudaGetSymbolAddress((void**)&pY2,    g_Y2);
    cudaGetSymbolAddress((void**)&pStats, g_statsAll);
    __half* pWf;
    cudaGetSymbolAddress((void**)&pWf, g_Wf);

    const int GEMM_GRID = (NN + GBM - 1) / GBM;      // 782
    const int EW_GRID   = (NN * 32) / 256;           // 6250
    const int ST_GRID   = (NN + SROWS - 1) / SROWS;  // 196

    // launch order keeps the embedding GEMM at index 3 (ncu profiles it)
    k_zero_all<<<(NN + 255) / 256, 256>>>();                         // 0
    k_hist<<<(NE + 255) / 256, 256>>>(dst);                          // 1
    k_prepW<<<dim3(64, 9), 256>>>(W_embed, W1, W2);                  // 2
    k_hgemm<false, false, true><<<GEMM_GRID, 256>>>(                 // 3 <- profiled
        h, pWf, b_embed, nullptr, nullptr, nullptr, nullptr, pH);
    k_scan1<<<SCAN_BLKS, 256>>>();                                   // 4
    k_scan23<<<SCAN_BLKS, 256>>>();                                  // 5
    k_fill<<<(NE + 255) / 256, 256>>>(src, dst);                     // 6

    for (int i = 0; i < LL; i++) {
        float* st0 = pStats + (i * 3 + 0) * 2 * D;
        float* st1 = pStats + (i * 3 + 1) * 2 * D;
        float* st2 = pStats + (i * 3 + 2) * 2 * D;

        k_agg<<<EW_GRID, 256>>>(eps, i);
        k_hgemm<false, true, false><<<GEMM_GRID, 256>>>(
            pX, pWf + (1 + i) * 16384, b1 + i * D,
            nullptr, nullptr, nullptr, st0, pY1);
        k_hgemm<true, true, false><<<GEMM_GRID, 256>>>(
            pY1, pWf + (5 + i) * 16384, b2 + i * D,
            g1 + i * D, be1 + i * D, st0, st1, pY2);
        k_bnrelu_stats<<<ST_GRID, 256>>>(ga + i * D, ba + i * D, st1, st2);
        float* out = (i == LL - 1) ? (float*)d_out : pH;
        k_residual<<<EW_GRID, 256>>>(ga + i * D, ba + i * D, gl + i * D, bl + i * D,
                                     st1, st2, out, (i == LL - 1) ? 0 : 1);
    }
}

// round 16
// speedup vs baseline: 1.2505x; 1.2505x over previous
#include <cuda_runtime.h>
#include <cuda_bf16.h>
#include <cuda_fp16.h>
#include <cstdint>

#define NN 50000
#define NE 1600000
#define D 128
#define LL 4
#define BN_EPS 1e-5f
#define SCAN_BLKS 196

// ---------------- device scratch ----------------
__device__ float g_H [NN * D];
__device__ float g_X [NN * D];
__device__ float g_Y1[NN * D];
__device__ float g_Y2[NN * D];
__device__ __half g_Hh[NN * D];     // fp16 mirror of H for the gather

__device__ int   g_deg   [NN];
__device__ int   g_rowptr[NN + 1];
__device__ int   g_cursor[NN];
__device__ int   g_col   [NE];
__device__ int   g_bsum  [256];

// per-layer stats: [layer][stage 0..2][sum|sumsq][D]
__device__ float g_statsAll[LL * 3 * 2 * D];

// pre-transposed fp16 weights [mat][n][k]: 0=embed, 1..4=W1, 5..8=W2
__device__ __half g_Wf[9 * 16384];

// ---------------- helpers ----------------
__device__ __forceinline__ uint32_t pack_f16_hi(float a, float b, float& ra, float& rb) {
    __half ha = __float2half_rn(a);
    __half hb = __float2half_rn(b);
    ra = a - __half2float(ha);
    rb = b - __half2float(hb);
    return (uint32_t)__half_as_ushort(ha) | ((uint32_t)__half_as_ushort(hb) << 16);
}
__device__ __forceinline__ uint32_t pack_f16(float a, float b) {
    return (uint32_t)__half_as_ushort(__float2half_rn(a))
         | ((uint32_t)__half_as_ushort(__float2half_rn(b)) << 16);
}
#define MMA16816(c, a, b)                                                      \
    asm volatile(                                                              \
        "mma.sync.aligned.m16n8k16.row.col.f32.f16.f16.f32 "                   \
        "{%0,%1,%2,%3}, {%4,%5,%6,%7}, {%8,%9}, {%0,%1,%2,%3};"                \
        : "+f"((c)[0]), "+f"((c)[1]), "+f"((c)[2]), "+f"((c)[3])               \
        : "r"((a)[0]), "r"((a)[1]), "r"((a)[2]), "r"((a)[3]),                  \
          "r"((b)[0]), "r"((b)[1]))
#define LDSM_X4(r0, r1, r2, r3, addr)                                          \
    asm volatile(                                                              \
        "ldmatrix.sync.aligned.m8n8.x4.shared.b16 {%0,%1,%2,%3}, [%4];"        \
        : "=r"(r0), "=r"(r1), "=r"(r2), "=r"(r3) : "r"(addr))

// ---------------- upfront zero ----------------
__global__ void k_zero_all() {
    int i = blockIdx.x * blockDim.x + threadIdx.x;
    if (i < NN) g_deg[i] = 0;
    if (i < LL * 3 * 2 * D) g_statsAll[i] = 0.f;
}

// ---------------- weight prep: fp32 W[k][n] -> fp16 at [n][k] ----------------
__global__ void k_prepW(const float* __restrict__ We, const float* __restrict__ W1,
                        const float* __restrict__ W2) {
    int mat = blockIdx.y;
    const float* src = (mat == 0) ? We : (mat < 5) ? (W1 + (mat - 1) * D * D)
                                                   : (W2 + (mat - 5) * D * D);
    int idx = blockIdx.x * 256 + threadIdx.x;   // over [k][n]
    int k = idx >> 7, n = idx & 127;
    g_Wf[mat * 16384 + n * 128 + k] = __float2half_rn(src[idx]);
}

// ---------------- CSR build ----------------
__global__ void k_hist(const int* __restrict__ dst) {
    int e = blockIdx.x * blockDim.x + threadIdx.x;
    if (e < NE) atomicAdd(&g_deg[dst[e]], 1);
}

__global__ void __launch_bounds__(256) k_scan1() {
    __shared__ int sh[256];
    int t = threadIdx.x;
    int i = blockIdx.x * 256 + t;
    int d = (i < NN) ? g_deg[i] : 0;
    sh[t] = d;
    __syncthreads();
#pragma unroll
    for (int off = 1; off < 256; off <<= 1) {
        int v = (t >= off) ? sh[t - off] : 0;
        __syncthreads();
        sh[t] += v;
        __syncthreads();
    }
    if (i < NN) g_rowptr[i] = sh[t] - d;
    if (t == 255) g_bsum[blockIdx.x] = sh[255];
}

// merged scan2+scan3
__global__ void __launch_bounds__(256) k_scan23() {
    __shared__ int sh[256];
    int t = threadIdx.x;
    int v0 = (t < SCAN_BLKS) ? g_bsum[t] : 0;
    sh[t] = v0;
    __syncthreads();
#pragma unroll
    for (int off = 1; off < 256; off <<= 1) {
        int v = (t >= off) ? sh[t - off] : 0;
        __syncthreads();
        sh[t] += v;
        __syncthreads();
    }
    int excl = sh[blockIdx.x] - g_bsum[blockIdx.x];
    int i = blockIdx.x * 256 + t;
    if (i < NN) {
        int v = g_rowptr[i] + excl;
        g_rowptr[i] = v;
        g_cursor[i] = v;
    }
    if (i == 0) g_rowptr[NN] = NE;
}

__global__ void k_fill(const int* __restrict__ src, const int* __restrict__ dst) {
    int e = blockIdx.x * blockDim.x + threadIdx.x;
    if (e < NE) {
        int p = atomicAdd(&g_cursor[dst[e]], 1);
        g_col[p] = src[e];
    }
}

// ---------------- aggregation: fp32 self term + fp16 neighbor gather, MLP=8 ----------------
__global__ void k_agg(const float* __restrict__ eps, int layer) {
    int gw   = (blockIdx.x * blockDim.x + threadIdx.x) >> 5;
    int lane = threadIdx.x & 31;
    if (gw >= NN) return;
    float sc = 1.0f + eps[layer];
    float4 a = ((const float4*)g_H)[gw * 32 + lane];
    float4 acc;
    acc.x = sc * a.x; acc.y = sc * a.y; acc.z = sc * a.z; acc.w = sc * a.w;
    const uint2* __restrict__ Hh2 = (const uint2*)g_Hh;
    int e = g_rowptr[gw], eE = g_rowptr[gw + 1];
    for (; e + 8 <= eE; e += 8) {
        int s0 = g_col[e + 0], s1 = g_col[e + 1], s2 = g_col[e + 2], s3 = g_col[e + 3];
        int s4 = g_col[e + 4], s5 = g_col[e + 5], s6 = g_col[e + 6], s7 = g_col[e + 7];
        uint2 v0 = Hh2[s0 * 32 + lane];
        uint2 v1 = Hh2[s1 * 32 + lane];
        uint2 v2 = Hh2[s2 * 32 + lane];
        uint2 v3 = Hh2[s3 * 32 + lane];
        uint2 v4 = Hh2[s4 * 32 + lane];
        uint2 v5 = Hh2[s5 * 32 + lane];
        uint2 v6 = Hh2[s6 * 32 + lane];
        uint2 v7 = Hh2[s7 * 32 + lane];
        float2 a0 = __half22float2(*(const __half2*)&v0.x), b0 = __half22float2(*(const __half2*)&v0.y);
        float2 a1 = __half22float2(*(const __half2*)&v1.x), b1 = __half22float2(*(const __half2*)&v1.y);
        float2 a2 = __half22float2(*(const __half2*)&v2.x), b2 = __half22float2(*(const __half2*)&v2.y);
        float2 a3 = __half22float2(*(const __half2*)&v3.x), b3 = __half22float2(*(const __half2*)&v3.y);
        float2 a4 = __half22float2(*(const __half2*)&v4.x), b4 = __half22float2(*(const __half2*)&v4.y);
        float2 a5 = __half22float2(*(const __half2*)&v5.x), b5 = __half22float2(*(const __half2*)&v5.y);
        float2 a6 = __half22float2(*(const __half2*)&v6.x), b6 = __half22float2(*(const __half2*)&v6.y);
        float2 a7 = __half22float2(*(const __half2*)&v7.x), b7 = __half22float2(*(const __half2*)&v7.y);
        acc.x += ((a0.x + a1.x) + (a2.x + a3.x)) + ((a4.x + a5.x) + (a6.x + a7.x));
        acc.y += ((a0.y + a1.y) + (a2.y + a3.y)) + ((a4.y + a5.y) + (a6.y + a7.y));
        acc.z += ((b0.x + b1.x) + (b2.x + b3.x)) + ((b4.x + b5.x) + (b6.x + b7.x));
        acc.w += ((b0.y + b1.y) + (b2.y + b3.y)) + ((b4.y + b5.y) + (b6.y + b7.y));
    }
    for (; e + 4 <= eE; e += 4) {
        int s0 = g_col[e + 0], s1 = g_col[e + 1], s2 = g_col[e + 2], s3 = g_col[e + 3];
        uint2 v0 = Hh2[s0 * 32 + lane];
        uint2 v1 = Hh2[s1 * 32 + lane];
        uint2 v2 = Hh2[s2 * 32 + lane];
        uint2 v3 = Hh2[s3 * 32 + lane];
        float2 a0 = __half22float2(*(const __half2*)&v0.x), b0 = __half22float2(*(const __half2*)&v0.y);
        float2 a1 = __half22float2(*(const __half2*)&v1.x), b1 = __half22float2(*(const __half2*)&v1.y);
        float2 a2 = __half22float2(*(const __half2*)&v2.x), b2 = __half22float2(*(const __half2*)&v2.y);
        float2 a3 = __half22float2(*(const __half2*)&v3.x), b3 = __half22float2(*(const __half2*)&v3.y);
        acc.x += (a0.x + a1.x) + (a2.x + a3.x);
        acc.y += (a0.y + a1.y) + (a2.y + a3.y);
        acc.z += (b0.x + b1.x) + (b2.x + b3.x);
        acc.w += (b0.y + b1.y) + (b2.y + b3.y);
    }
    for (; e < eE; e++) {
        uint2 v = Hh2[g_col[e] * 32 + lane];
        float2 aa = __half22float2(*(const __half2*)&v.x);
        float2 bb = __half22float2(*(const __half2*)&v.y);
        acc.x += aa.x; acc.y += aa.y; acc.z += bb.x; acc.w += bb.y;
    }
    ((float4*)g_X)[gw * 32 + lane] = acc;
}

// ---------------- HMMA GEMM: C[M,128] = A[M,128] @ W[128,128] + bias ----------------
// fp16 2-term split: A = Ah + Al (fp16), W single fp16. D = Ah@W + Al@W.
// BM=64, BN=128, BK=16 double-buffered smem; register staging (R3/R13 pattern).
// Stride 24 rows: 48B, 16B-aligned, ldmatrix conflict-free.
#define ASTR 24
#define GBM 64

template <bool NORM, bool STATS, bool MIRROR>
__global__ void __launch_bounds__(256, 3) k_hgemm(
    const float* __restrict__ Ain,
    const __half* __restrict__ Wf,
    const float* __restrict__ bias,
    const float* __restrict__ gam, const float* __restrict__ bet,
    const float* __restrict__ statIn, float* __restrict__ statOut,
    float* __restrict__ C)
{
    __shared__ __align__(16) unsigned char smraw[26624];
    __half* AhS = (__half*)smraw;                          // [2][64][ASTR] = 6144B
    __half* AlS = AhS + 2 * 64 * ASTR;                     // 6144B
    __half* WS  = AlS + 2 * 64 * ASTR;                     // [2][128][ASTR] = 12288B
    float* nrm = (float*)(smraw + 24576);                  // 4 x 128 = 2048B
    float* red = (float*)smraw;                            // epilogue overlay [16][128]

    const int tid  = threadIdx.x;
    const int lane = tid & 31;
    const int w    = tid >> 5;
    const int wm   = w >> 2;       // 0..1 (32-row block)
    const int wn   = w & 3;        // 0..3 (32-col block)
    const int row0 = blockIdx.x * GBM;
    const int arow = tid >> 2;     // 0..63  (A load row)
    const int ac   = (tid & 3) * 4;// A k-offset within 16
    const int wrow = tid >> 1;     // 0..127 (W load row)
    const int wk   = (tid & 1) * 8;// W k-offset within 16

    if (NORM) {
        if (tid < 128) {
            float s = statIn[tid], q = statIn[128 + tid];
            float mu  = s * (1.0f / NN);
            float var = q * (1.0f / NN) - mu * mu;
            nrm[tid]       = mu;
            nrm[128 + tid] = rsqrtf(var + BN_EPS);
            nrm[256 + tid] = gam[tid];
            nrm[384 + tid] = bet[tid];
        }
        __syncthreads();
    }

    const bool rowOK = (row0 + arow) < NN;
    const float* aSrc = Ain + (size_t)(row0 + arow) * 128 + ac;
    const __half* wSrc = Wf + wrow * 128 + wk;

    // ldmatrix per-lane offsets
    const int a_row = wm * 32 + (lane & 15);                       // + m*16
    const int a_ko  = (lane >> 4) << 3;                            // 0 or 8
    const int b_row = wn * 32 + (lane & 7) + ((lane >> 4) << 3);   // + g*16
    const int b_ko  = ((lane >> 3) & 1) << 3;                      // 0 or 8

    float va[4];
    uint4 vw;

#define LD(K0) do {                                                            \
    if (rowOK) {                                                               \
        float4 f = *(const float4*)(aSrc + (K0));                              \
        va[0] = f.x; va[1] = f.y; va[2] = f.z; va[3] = f.w;                    \
    } else { va[0] = va[1] = va[2] = va[3] = 0.f; }                            \
    vw = *(const uint4*)(wSrc + (K0));                                         \
} while (0)

#define ST(BUF, K0) do {                                                       \
    float v0 = va[0], v1 = va[1], v2 = va[2], v3 = va[3];                      \
    if (NORM) {                                                                \
        int cc = (K0) + ac;                                                    \
        v0 = fmaxf(fmaf(nrm[256 + cc + 0] * (v0 - nrm[cc + 0]),               \
                        nrm[128 + cc + 0], nrm[384 + cc + 0]), 0.f);           \
        v1 = fmaxf(fmaf(nrm[256 + cc + 1] * (v1 - nrm[cc + 1]),               \
                        nrm[128 + cc + 1], nrm[384 + cc + 1]), 0.f);           \
        v2 = fmaxf(fmaf(nrm[256 + cc + 2] * (v2 - nrm[cc + 2]),               \
                        nrm[128 + cc + 2], nrm[384 + cc + 2]), 0.f);           \
        v3 = fmaxf(fmaf(nrm[256 + cc + 3] * (v3 - nrm[cc + 3]),               \
                        nrm[128 + cc + 3], nrm[384 + cc + 3]), 0.f);           \
    }                                                                          \
    float r0, r1, r2, r3;                                                      \
    uint32_t h0 = pack_f16_hi(v0, v1, r0, r1);                                 \
    uint32_t h1 = pack_f16_hi(v2, v3, r2, r3);                                 \
    uint32_t l0 = pack_f16(r0, r1);                                            \
    uint32_t l1 = pack_f16(r2, r3);                                            \
    *(uint2*)&AhS[(BUF) * 64 * ASTR + arow * ASTR + ac] = make_uint2(h0, h1);  \
    *(uint2*)&AlS[(BUF) * 64 * ASTR + arow * ASTR + ac] = make_uint2(l0, l1);  \
    *(uint4*)&WS[(BUF) * 128 * ASTR + wrow * ASTR + wk] = vw;                  \
} while (0)

    LD(0);
    ST(0, 0);
    __syncthreads();

    float acc[2][4][4];
#pragma unroll
    for (int m = 0; m < 2; m++)
#pragma unroll
        for (int n = 0; n < 4; n++)
#pragma unroll
            for (int j = 0; j < 4; j++) acc[m][n][j] = 0.f;

#pragma unroll
    for (int t = 0; t < 8; t++) {
        const int buf = t & 1;
        if (t < 7) LD((t + 1) * 16);

        uint32_t ah[2][4], al[2][4];
#pragma unroll
        for (int m = 0; m < 2; m++) {
            uint32_t pa = (uint32_t)__cvta_generic_to_shared(
                &AhS[buf * 64 * ASTR + (a_row + m * 16) * ASTR + a_ko]);
            LDSM_X4(ah[m][0], ah[m][1], ah[m][2], ah[m][3], pa);
            uint32_t pl = (uint32_t)__cvta_generic_to_shared(
                &AlS[buf * 64 * ASTR + (a_row + m * 16) * ASTR + a_ko]);
            LDSM_X4(al[m][0], al[m][1], al[m][2], al[m][3], pl);
        }
        uint32_t bh[4][2];
#pragma unroll
        for (int g = 0; g < 2; g++) {
            uint32_t pb = (uint32_t)__cvta_generic_to_shared(
                &WS[buf * 128 * ASTR + (b_row + g * 16) * ASTR + b_ko]);
            LDSM_X4(bh[2 * g][0], bh[2 * g][1], bh[2 * g + 1][0], bh[2 * g + 1][1], pb);
        }
#pragma unroll
        for (int m = 0; m < 2; m++)
#pragma unroll
            for (int n = 0; n < 4; n++) {
                MMA16816(acc[m][n], ah[m], bh[n]);
                MMA16816(acc[m][n], al[m], bh[n]);
            }
        if (t < 7) ST(buf ^ 1, (t + 1) * 16);
        __syncthreads();
    }

#undef LD
#undef ST

    // ---- epilogue: bias + store + optional column stats ----
    float ps[4][2], pq[4][2];
    if (STATS) {
#pragma unroll
        for (int n = 0; n < 4; n++) { ps[n][0] = ps[n][1] = 0.f; pq[n][0] = pq[n][1] = 0.f; }
    }
#pragma unroll
    for (int m = 0; m < 2; m++) {
        int ra = row0 + wm * 32 + m * 16 + (lane >> 2);
        int rb = ra + 8;
        bool vva = ra < NN, vvb = rb < NN;
#pragma unroll
        for (int n = 0; n < 4; n++) {
            int col = wn * 32 + n * 8 + ((lane & 3) << 1);
            float2 b2 = *(const float2*)&bias[col];
            float o0 = acc[m][n][0] + b2.x, o1 = acc[m][n][1] + b2.y;
            float o2 = acc[m][n][2] + b2.x, o3 = acc[m][n][3] + b2.y;
            if (vva) {
                *(float2*)&C[ra * 128 + col] = make_float2(o0, o1);
                if (MIRROR) {
                    __half2 hh = __floats2half2_rn(o0, o1);
                    *(__half2*)&g_Hh[ra * 128 + col] = hh;
                }
            }
            if (vvb) {
                *(float2*)&C[rb * 128 + col] = make_float2(o2, o3);
                if (MIRROR) {
                    __half2 hh = __floats2half2_rn(o2, o3);
                    *(__half2*)&g_Hh[rb * 128 + col] = hh;
                }
            }
            if (STATS) {
                if (vva) { ps[n][0] += o0; pq[n][0] += o0 * o0; ps[n][1] += o1; pq[n][1] += o1 * o1; }
                if (vvb) { ps[n][0] += o2; pq[n][0] += o2 * o2; ps[n][1] += o3; pq[n][1] += o3 * o3; }
            }
        }
    }
    if (STATS) {
        const int contrib = wm * 8 + (lane >> 2);   // 0..15
        __syncthreads();
#pragma unroll
        for (int n = 0; n < 4; n++) {
            int col = wn * 32 + n * 8 + ((lane & 3) << 1);
            red[contrib * 128 + col]     = ps[n][0];
            red[contrib * 128 + col + 1] = ps[n][1];
        }
        __syncthreads();
        if (tid < 128) {
            float s = 0.f;
#pragma unroll
            for (int g = 0; g < 16; g++) s += red[g * 128 + tid];
            atomicAdd(&statOut[tid], s);
        }
        __syncthreads();
#pragma unroll
        for (int n = 0; n < 4; n++) {
            int col = wn * 32 + n * 8 + ((lane & 3) << 1);
            red[contrib * 128 + col]     = pq[n][0];
            red[contrib * 128 + col + 1] = pq[n][1];
        }
        __syncthreads();
        if (tid < 128) {
            float s = 0.f;
#pragma unroll
            for (int g = 0; g < 16; g++) s += red[g * 128 + tid];
            atomicAdd(&statOut[128 + tid], s);
        }
    }
}

// ---------------- stats of A = relu(BN(Y2; st1)) -> statOut ----------------
#define SROWS 256
__global__ void __launch_bounds__(256) k_bnrelu_stats(
    const float* __restrict__ gam, const float* __restrict__ bet,
    const float* __restrict__ statIn, float* __restrict__ statOut)
{
    int tid = threadIdx.x;
    int c4  = tid & 31;
    int rg  = tid >> 5;
    int cc  = c4 * 4;
    float4 s4 = *(const float4*)&statIn[cc];
    float4 q4 = *(const float4*)&statIn[128 + cc];
    float4 m4, r4;
    m4.x = s4.x * (1.0f / NN); r4.x = rsqrtf(q4.x * (1.0f / NN) - m4.x * m4.x + BN_EPS);
    m4.y = s4.y * (1.0f / NN); r4.y = rsqrtf(q4.y * (1.0f / NN) - m4.y * m4.y + BN_EPS);
    m4.z = s4.z * (1.0f / NN); r4.z = rsqrtf(q4.z * (1.0f / NN) - m4.z * m4.z + BN_EPS);
    m4.w = s4.w * (1.0f / NN); r4.w = rsqrtf(q4.w * (1.0f / NN) - m4.w * m4.w + BN_EPS);
    float4 g4 = *(const float4*)&gam[cc];
    float4 b4 = *(const float4*)&bet[cc];
    float s[4] = {0.f, 0.f, 0.f, 0.f}, q[4] = {0.f, 0.f, 0.f, 0.f};
    int rEnd = min(blockIdx.x * SROWS + SROWS, NN);
    for (int r = blockIdx.x * SROWS + rg; r < rEnd; r += 8) {
        float4 v = *(const float4*)&g_Y2[r * 128 + cc];
        float4 a;
        a.x = fmaxf(fmaf(g4.x * (v.x - m4.x), r4.x, b4.x), 0.f);
        a.y = fmaxf(fmaf(g4.y * (v.y - m4.y), r4.y, b4.y), 0.f);
        a.z = fmaxf(fmaf(g4.z * (v.z - m4.z), r4.z, b4.z), 0.f);
        a.w = fmaxf(fmaf(g4.w * (v.w - m4.w), r4.w, b4.w), 0.f);
        s[0] += a.x; q[0] += a.x * a.x;
        s[1] += a.y; q[1] += a.y * a.y;
        s[2] += a.z; q[2] += a.z * a.z;
        s[3] += a.w; q[3] += a.w * a.w;
    }
    __shared__ float shs[8][128];
    __shared__ float shq[8][128];
#pragma unroll
    for (int j = 0; j < 4; j++) { shs[rg][cc + j] = s[j]; shq[rg][cc + j] = q[j]; }
    __syncthreads();
    if (tid < 128) {
        float ts = 0.f, tq = 0.f;
#pragma unroll
        for (int g = 0; g < 8; g++) { ts += shs[g][tid]; tq += shq[g][tid]; }
        atomicAdd(&statOut[tid],       ts);
        atomicAdd(&statOut[128 + tid], tq);
    }
}

// ---------------- Hout = H + relu(BN(relu(BN(Y2; st1)); st2)); optional fp16 mirror ----------------
__global__ void __launch_bounds__(256) k_residual(
    const float* __restrict__ ga, const float* __restrict__ ba,
    const float* __restrict__ gl, const float* __restrict__ bl,
    const float* __restrict__ st1, const float* __restrict__ st2,
    float* __restrict__ out, int writeH)
{
    int i4 = blockIdx.x * blockDim.x + threadIdx.x;
    if (i4 >= NN * 32) return;
    int cc = (i4 & 31) * 4;
    float4 s4 = *(const float4*)&st1[cc];
    float4 q4 = *(const float4*)&st1[128 + cc];
    float4 m1, r1;
    m1.x = s4.x * (1.0f / NN); r1.x = rsqrtf(q4.x * (1.0f / NN) - m1.x * m1.x + BN_EPS);
    m1.y = s4.y * (1.0f / NN); r1.y = rsqrtf(q4.y * (1.0f / NN) - m1.y * m1.y + BN_EPS);
    m1.z = s4.z * (1.0f / NN); r1.z = rsqrtf(q4.z * (1.0f / NN) - m1.z * m1.z + BN_EPS);
    m1.w = s4.w * (1.0f / NN); r1.w = rsqrtf(q4.w * (1.0f / NN) - m1.w * m1.w + BN_EPS);
    float4 ga4 = *(const float4*)&ga[cc];
    float4 ba4 = *(const float4*)&ba[cc];
    float4 t4 = *(const float4*)&st2[cc];
    float4 u4 = *(const float4*)&st2[128 + cc];
    float4 m2, r2;
    m2.x = t4.x * (1.0f / NN); r2.x = rsqrtf(u4.x * (1.0f / NN) - m2.x * m2.x + BN_EPS);
    m2.y = t4.y * (1.0f / NN); r2.y = rsqrtf(u4.y * (1.0f / NN) - m2.y * m2.y + BN_EPS);
    m2.z = t4.z * (1.0f / NN); r2.z = rsqrtf(u4.z * (1.0f / NN) - m2.z * m2.z + BN_EPS);
    m2.w = t4.w * (1.0f / NN); r2.w = rsqrtf(u4.w * (1.0f / NN) - m2.w * m2.w + BN_EPS);
    float4 gl4 = *(const float4*)&gl[cc];
    float4 bl4 = *(const float4*)&bl[cc];

    float4 v = ((const float4*)g_Y2)[i4];
    float4 h = ((const float4*)g_H)[i4];
    float4 a, o;
    a.x = fmaxf(fmaf(ga4.x * (v.x - m1.x), r1.x, ba4.x), 0.f);
    a.y = fmaxf(fmaf(ga4.y * (v.y - m1.y), r1.y, ba4.y), 0.f);
    a.z = fmaxf(fmaf(ga4.z * (v.z - m1.z), r1.z, ba4.z), 0.f);
    a.w = fmaxf(fmaf(ga4.w * (v.w - m1.w), r1.w, ba4.w), 0.f);
    o.x = h.x + fmaxf(fmaf(gl4.x * (a.x - m2.x), r2.x, bl4.x), 0.f);
    o.y = h.y + fmaxf(fmaf(gl4.y * (a.y - m2.y), r2.y, bl4.y), 0.f);
    o.z = h.z + fmaxf(fmaf(gl4.z * (a.z - m2.z), r2.z, bl4.z), 0.f);
    o.w = h.w + fmaxf(fmaf(gl4.w * (a.w - m2.w), r2.w, bl4.w), 0.f);
    ((float4*)out)[i4] = o;
    if (writeH) {
        __half2 h01 = __floats2half2_rn(o.x, o.y);
        __half2 h23 = __floats2half2_rn(o.z, o.w);
        uint2 u;
        u.x = *(uint32_t*)&h01;
        u.y = *(uint32_t*)&h23;
        ((uint2*)g_Hh)[i4] = u;
    }
}

// ---------------- launcher ----------------
extern "C" void kernel_launch(void* const* d_in, const int* in_sizes, int n_in,
                              void* d_out, int out_size)
{
    const float* h       = (const float*)d_in[0];
    const int*   src     = (const int*)  d_in[1];
    const int*   dst     = (const int*)  d_in[2];
    const float* W_embed = (const float*)d_in[3];
    const float* b_embed = (const float*)d_in[4];
    const float* eps     = (const float*)d_in[5];
    const float* W1      = (const float*)d_in[6];
    const float* b1      = (const float*)d_in[7];
    const float* g1      = (const float*)d_in[8];
    const float* be1     = (const float*)d_in[9];
    const float* W2      = (const float*)d_in[10];
    const float* b2      = (const float*)d_in[11];
    const float* ga      = (const float*)d_in[12];
    const float* ba      = (const float*)d_in[13];
    const float* gl      = (const float*)d_in[14];
    const float* bl      = (const float*)d_in[15];

    float *pH, *pX, *pY1, *pY2, *pStats;
    cudaGetSymbolAddress((void**)&pH,     g_H);
    cudaGetSymbolAddress((void**)&pX,     g_X);
    cudaGetSymbolAddress((void**)&pY1,    g_Y1);
    cudaGetSymbolAddress((void**)&pY2,    g_Y2);
    cudaGetSymbolAddress((void**)&pStats, g_statsAll);
    __half* pWf;
    cudaGetSymbolAddress((void**)&pWf, g_Wf);

    const int GEMM_GRID = (NN + GBM - 1) / GBM;      // 782
    const int EW_GRID   = (NN * 32) / 256;           // 6250
    const int ST_GRID   = (NN + SROWS - 1) / SROWS;  // 196

    // launch order keeps the embedding GEMM at index 3 (ncu profiles it)
    k_zero_all<<<(NN + 255) / 256, 256>>>();                         // 0
    k_hist<<<(NE + 255) / 256, 256>>>(dst);                          // 1
    k_prepW<<<dim3(64, 9), 256>>>(W_embed, W1, W2);                  // 2
    k_hgemm<false, false, true><<<GEMM_GRID, 256>>>(                 // 3 <- profiled
        h, pWf, b_embed, nullptr, nullptr, nullptr, nullptr, pH);
    k_scan1<<<SCAN_BLKS, 256>>>();                                   // 4
    k_scan23<<<SCAN_BLKS, 256>>>();                                  // 5
    k_fill<<<(NE + 255) / 256, 256>>>(src, dst);                     // 6

    for (int i = 0; i < LL; i++) {
        float* st0 = pStats + (i * 3 + 0) * 2 * D;
        float* st1 = pStats + (i * 3 + 1) * 2 * D;
        float* st2 = pStats + (i * 3 + 2) * 2 * D;

        k_agg<<<EW_GRID, 256>>>(eps, i);
        k_hgemm<false, true, false><<<GEMM_GRID, 256>>>(
            pX, pWf + (1 + i) * 16384, b1 + i * D,
            nullptr, nullptr, nullptr, st0, pY1);
        k_hgemm<true, true, false><<<GEMM_GRID, 256>>>(
            pY1, pWf + (5 + i) * 16384, b2 + i * D,
            g1 + i * D, be1 + i * D, st0, st1, pY2);
        k_bnrelu_stats<<<ST_GRID, 256>>>(ga + i * D, ba + i * D, st1, st2);
        float* out = (i == LL - 1) ? (float*)d_out : pH;
        k_residual<<<EW_GRID, 256>>>(ga + i * D, ba + i * D, gl + i * D, bl + i * D,
                                     st1, st2, out, (i == LL - 1) ? 0 : 1);
    }
}

// round 17
// speedup vs baseline: 1.2845x; 1.0272x over previous
#include <cuda_runtime.h>
#include <cuda_bf16.h>
#include <cuda_fp16.h>
#include <cstdint>

#define NN 50000
#define NE 1600000
#define D 128
#define LL 4
#define BN_EPS 1e-5f
#define SCAN_BLKS 196

// ---------------- device scratch ----------------
__device__ float g_H [NN * D];
__device__ float g_X [NN * D];
__device__ float g_Y1[NN * D];
__device__ float g_Y2[NN * D];
__device__ __half g_Hh[NN * D];     // fp16 mirror of H for the gather

__device__ int   g_deg   [NN];
__device__ int   g_rowptr[NN + 1];
__device__ int   g_cursor[NN];
__device__ int   g_col   [NE];
__device__ int   g_bsum  [256];

// per-layer stats: [layer][stage 0..2][sum|sumsq][D]
__device__ float g_statsAll[LL * 3 * 2 * D];

// pre-transposed fp16 weights [mat][n][k]: 0=embed, 1..4=W1, 5..8=W2
__device__ __half g_Wf[9 * 16384];

// ---------------- helpers ----------------
__device__ __forceinline__ uint32_t pack_f16_hi(float a, float b, float& ra, float& rb) {
    __half ha = __float2half_rn(a);
    __half hb = __float2half_rn(b);
    ra = a - __half2float(ha);
    rb = b - __half2float(hb);
    return (uint32_t)__half_as_ushort(ha) | ((uint32_t)__half_as_ushort(hb) << 16);
}
__device__ __forceinline__ uint32_t pack_f16(float a, float b) {
    return (uint32_t)__half_as_ushort(__float2half_rn(a))
         | ((uint32_t)__half_as_ushort(__float2half_rn(b)) << 16);
}
#define MMA16816(c, a, b)                                                      \
    asm volatile(                                                              \
        "mma.sync.aligned.m16n8k16.row.col.f32.f16.f16.f32 "                   \
        "{%0,%1,%2,%3}, {%4,%5,%6,%7}, {%8,%9}, {%0,%1,%2,%3};"                \
        : "+f"((c)[0]), "+f"((c)[1]), "+f"((c)[2]), "+f"((c)[3])               \
        : "r"((a)[0]), "r"((a)[1]), "r"((a)[2]), "r"((a)[3]),                  \
          "r"((b)[0]), "r"((b)[1]))
#define LDSM_X4(r0, r1, r2, r3, addr)                                          \
    asm volatile(                                                              \
        "ldmatrix.sync.aligned.m8n8.x4.shared.b16 {%0,%1,%2,%3}, [%4];"        \
        : "=r"(r0), "=r"(r1), "=r"(r2), "=r"(r3) : "r"(addr))

// ---------------- upfront zero ----------------
__global__ void k_zero_all() {
    int i = blockIdx.x * blockDim.x + threadIdx.x;
    if (i < NN) g_deg[i] = 0;
    if (i < LL * 3 * 2 * D) g_statsAll[i] = 0.f;
}

// ---------------- weight prep: fp32 W[k][n] -> fp16 at [n][k] ----------------
__global__ void k_prepW(const float* __restrict__ We, const float* __restrict__ W1,
                        const float* __restrict__ W2) {
    int mat = blockIdx.y;
    const float* src = (mat == 0) ? We : (mat < 5) ? (W1 + (mat - 1) * D * D)
                                                   : (W2 + (mat - 5) * D * D);
    int idx = blockIdx.x * 256 + threadIdx.x;   // over [k][n]
    int k = idx >> 7, n = idx & 127;
    g_Wf[mat * 16384 + n * 128 + k] = __float2half_rn(src[idx]);
}

// ---------------- CSR build ----------------
__global__ void k_hist(const int* __restrict__ dst) {
    int e = blockIdx.x * blockDim.x + threadIdx.x;
    if (e < NE) atomicAdd(&g_deg[dst[e]], 1);
}

__global__ void __launch_bounds__(256) k_scan1() {
    __shared__ int sh[256];
    int t = threadIdx.x;
    int i = blockIdx.x * 256 + t;
    int d = (i < NN) ? g_deg[i] : 0;
    sh[t] = d;
    __syncthreads();
#pragma unroll
    for (int off = 1; off < 256; off <<= 1) {
        int v = (t >= off) ? sh[t - off] : 0;
        __syncthreads();
        sh[t] += v;
        __syncthreads();
    }
    if (i < NN) g_rowptr[i] = sh[t] - d;
    if (t == 255) g_bsum[blockIdx.x] = sh[255];
}

// merged scan2+scan3
__global__ void __launch_bounds__(256) k_scan23() {
    __shared__ int sh[256];
    int t = threadIdx.x;
    int v0 = (t < SCAN_BLKS) ? g_bsum[t] : 0;
    sh[t] = v0;
    __syncthreads();
#pragma unroll
    for (int off = 1; off < 256; off <<= 1) {
        int v = (t >= off) ? sh[t - off] : 0;
        __syncthreads();
        sh[t] += v;
        __syncthreads();
    }
    int excl = sh[blockIdx.x] - g_bsum[blockIdx.x];
    int i = blockIdx.x * 256 + t;
    if (i < NN) {
        int v = g_rowptr[i] + excl;
        g_rowptr[i] = v;
        g_cursor[i] = v;
    }
    if (i == 0) g_rowptr[NN] = NE;
}

__global__ void k_fill(const int* __restrict__ src, const int* __restrict__ dst) {
    int e = blockIdx.x * blockDim.x + threadIdx.x;
    if (e < NE) {
        int p = atomicAdd(&g_cursor[dst[e]], 1);
        g_col[p] = src[e];
    }
}

// ---------------- aggregation v2: two edges per gather instruction ----------------
// Lanes 0-15 cover edge e (uint4 each = full 256B row), lanes 16-31 cover edge e+1.
// Lane L accumulates 8 columns ((L&15)*8 ..+7); shfl_xor(16) merges halves at end.
__device__ __forceinline__ void acc8(float* acc, uint4 v) {
    float2 p0 = __half22float2(*(const __half2*)&v.x);
    float2 p1 = __half22float2(*(const __half2*)&v.y);
    float2 p2 = __half22float2(*(const __half2*)&v.z);
    float2 p3 = __half22float2(*(const __half2*)&v.w);
    acc[0] += p0.x; acc[1] += p0.y;
    acc[2] += p1.x; acc[3] += p1.y;
    acc[4] += p2.x; acc[5] += p2.y;
    acc[6] += p3.x; acc[7] += p3.y;
}

__global__ void k_agg(const float* __restrict__ eps, int layer) {
    int gw   = (blockIdx.x * blockDim.x + threadIdx.x) >> 5;  // node
    int lane = threadIdx.x & 31;
    if (gw >= NN) return;
    const int half = lane >> 4;     // 0: even edges, 1: odd edges
    const int l16  = lane & 15;     // uint4 index within row (8 columns)
    const uint4* __restrict__ Hh4 = (const uint4*)g_Hh;   // row stride 16 uint4

    float acc[8];
    if (half == 0) {
        // self term in half 0 only
        float sc = 1.0f + eps[layer];
        float4 a0 = ((const float4*)g_H)[gw * 32 + l16 * 2];
        float4 a1 = ((const float4*)g_H)[gw * 32 + l16 * 2 + 1];
        acc[0] = sc * a0.x; acc[1] = sc * a0.y; acc[2] = sc * a0.z; acc[3] = sc * a0.w;
        acc[4] = sc * a1.x; acc[5] = sc * a1.y; acc[6] = sc * a1.z; acc[7] = sc * a1.w;
    } else {
#pragma unroll
        for (int j = 0; j < 8; j++) acc[j] = 0.f;
    }

    int e = g_rowptr[gw], eE = g_rowptr[gw + 1];
    // 8 edges per iteration: each lane gathers 4 rows (its parity)
    for (; e + 8 <= eE; e += 8) {
        int s0 = g_col[e + 0 + half];
        int s1 = g_col[e + 2 + half];
        int s2 = g_col[e + 4 + half];
        int s3 = g_col[e + 6 + half];
        uint4 v0 = Hh4[s0 * 16 + l16];
        uint4 v1 = Hh4[s1 * 16 + l16];
        uint4 v2 = Hh4[s2 * 16 + l16];
        uint4 v3 = Hh4[s3 * 16 + l16];
        acc8(acc, v0);
        acc8(acc, v1);
        acc8(acc, v2);
        acc8(acc, v3);
    }
    // 2 edges per iteration
    for (; e + 2 <= eE; e += 2) {
        int s = g_col[e + half];
        uint4 v = Hh4[s * 16 + l16];
        acc8(acc, v);
    }
    // odd leftover: half 0 only
    if (e < eE && half == 0) {
        int s = g_col[e];
        uint4 v = Hh4[s * 16 + l16];
        acc8(acc, v);
    }
    // merge halves
#pragma unroll
    for (int j = 0; j < 8; j++)
        acc[j] += __shfl_xor_sync(0xFFFFFFFFu, acc[j], 16);
    // lanes 0-15 write the row
    if (half == 0) {
        ((float4*)g_X)[gw * 32 + l16 * 2]     = make_float4(acc[0], acc[1], acc[2], acc[3]);
        ((float4*)g_X)[gw * 32 + l16 * 2 + 1] = make_float4(acc[4], acc[5], acc[6], acc[7]);
    }
}

// ---------------- HMMA GEMM: C[M,128] = A[M,128] @ W[128,128] + bias ----------------
// fp16 2-term split: A = Ah + Al (fp16), W single fp16. D = Ah@W + Al@W.
// BM=64, BN=128, BK=16 double-buffered smem; register staging (R3/R13 pattern).
// Stride 24 rows: 48B, 16B-aligned, ldmatrix conflict-free.
#define ASTR 24
#define GBM 64

template <bool NORM, bool STATS, bool MIRROR>
__global__ void __launch_bounds__(256, 3) k_hgemm(
    const float* __restrict__ Ain,
    const __half* __restrict__ Wf,
    const float* __restrict__ bias,
    const float* __restrict__ gam, const float* __restrict__ bet,
    const float* __restrict__ statIn, float* __restrict__ statOut,
    float* __restrict__ C)
{
    __shared__ __align__(16) unsigned char smraw[26624];
    __half* AhS = (__half*)smraw;                          // [2][64][ASTR] = 6144B
    __half* AlS = AhS + 2 * 64 * ASTR;                     // 6144B
    __half* WS  = AlS + 2 * 64 * ASTR;                     // [2][128][ASTR] = 12288B
    float* nrm = (float*)(smraw + 24576);                  // 4 x 128 = 2048B
    float* red = (float*)smraw;                            // epilogue overlay [16][128]

    const int tid  = threadIdx.x;
    const int lane = tid & 31;
    const int w    = tid >> 5;
    const int wm   = w >> 2;       // 0..1 (32-row block)
    const int wn   = w & 3;        // 0..3 (32-col block)
    const int row0 = blockIdx.x * GBM;
    const int arow = tid >> 2;     // 0..63  (A load row)
    const int ac   = (tid & 3) * 4;// A k-offset within 16
    const int wrow = tid >> 1;     // 0..127 (W load row)
    const int wk   = (tid & 1) * 8;// W k-offset within 16

    if (NORM) {
        if (tid < 128) {
            float s = statIn[tid], q = statIn[128 + tid];
            float mu  = s * (1.0f / NN);
            float var = q * (1.0f / NN) - mu * mu;
            nrm[tid]       = mu;
            nrm[128 + tid] = rsqrtf(var + BN_EPS);
            nrm[256 + tid] = gam[tid];
            nrm[384 + tid] = bet[tid];
        }
        __syncthreads();
    }

    const bool rowOK = (row0 + arow) < NN;
    const float* aSrc = Ain + (size_t)(row0 + arow) * 128 + ac;
    const __half* wSrc = Wf + wrow * 128 + wk;

    // ldmatrix per-lane offsets
    const int a_row = wm * 32 + (lane & 15);                       // + m*16
    const int a_ko  = (lane >> 4) << 3;                            // 0 or 8
    const int b_row = wn * 32 + (lane & 7) + ((lane >> 4) << 3);   // + g*16
    const int b_ko  = ((lane >> 3) & 1) << 3;                      // 0 or 8

    float va[4];
    uint4 vw;

#define LD(K0) do {                                                            \
    if (rowOK) {                                                               \
        float4 f = *(const float4*)(aSrc + (K0));                              \
        va[0] = f.x; va[1] = f.y; va[2] = f.z; va[3] = f.w;                    \
    } else { va[0] = va[1] = va[2] = va[3] = 0.f; }                            \
    vw = *(const uint4*)(wSrc + (K0));                                         \
} while (0)

#define ST(BUF, K0) do {                                                       \
    float v0 = va[0], v1 = va[1], v2 = va[2], v3 = va[3];                      \
    if (NORM) {                                                                \
        int cc = (K0) + ac;                                                    \
        v0 = fmaxf(fmaf(nrm[256 + cc + 0] * (v0 - nrm[cc + 0]),               \
                        nrm[128 + cc + 0], nrm[384 + cc + 0]), 0.f);           \
        v1 = fmaxf(fmaf(nrm[256 + cc + 1] * (v1 - nrm[cc + 1]),               \
                        nrm[128 + cc + 1], nrm[384 + cc + 1]), 0.f);           \
        v2 = fmaxf(fmaf(nrm[256 + cc + 2] * (v2 - nrm[cc + 2]),               \
                        nrm[128 + cc + 2], nrm[384 + cc + 2]), 0.f);           \
        v3 = fmaxf(fmaf(nrm[256 + cc + 3] * (v3 - nrm[cc + 3]),               \
                        nrm[128 + cc + 3], nrm[384 + cc + 3]), 0.f);           \
    }                                                                          \
    float r0, r1, r2, r3;                                                      \
    uint32_t h0 = pack_f16_hi(v0, v1, r0, r1);                                 \
    uint32_t h1 = pack_f16_hi(v2, v3, r2, r3);                                 \
    uint32_t l0 = pack_f16(r0, r1);                                            \
    uint32_t l1 = pack_f16(r2, r3);                                            \
    *(uint2*)&AhS[(BUF) * 64 * ASTR + arow * ASTR + ac] = make_uint2(h0, h1);  \
    *(uint2*)&AlS[(BUF) * 64 * ASTR + arow * ASTR + ac] = make_uint2(l0, l1);  \
    *(uint4*)&WS[(BUF) * 128 * ASTR + wrow * ASTR + wk] = vw;                  \
} while (0)

    LD(0);
    ST(0, 0);
    __syncthreads();

    float acc[2][4][4];
#pragma unroll
    for (int m = 0; m < 2; m++)
#pragma unroll
        for (int n = 0; n < 4; n++)
#pragma unroll
            for (int j = 0; j < 4; j++) acc[m][n][j] = 0.f;

#pragma unroll
    for (int t = 0; t < 8; t++) {
        const int buf = t & 1;
        if (t < 7) LD((t + 1) * 16);

        uint32_t ah[2][4], al[2][4];
#pragma unroll
        for (int m = 0; m < 2; m++) {
            uint32_t pa = (uint32_t)__cvta_generic_to_shared(
                &AhS[buf * 64 * ASTR + (a_row + m * 16) * ASTR + a_ko]);
            LDSM_X4(ah[m][0], ah[m][1], ah[m][2], ah[m][3], pa);
            uint32_t pl = (uint32_t)__cvta_generic_to_shared(
                &AlS[buf * 64 * ASTR + (a_row + m * 16) * ASTR + a_ko]);
            LDSM_X4(al[m][0], al[m][1], al[m][2], al[m][3], pl);
        }
        uint32_t bh[4][2];
#pragma unroll
        for (int g = 0; g < 2; g++) {
            uint32_t pb = (uint32_t)__cvta_generic_to_shared(
                &WS[buf * 128 * ASTR + (b_row + g * 16) * ASTR + b_ko]);
            LDSM_X4(bh[2 * g][0], bh[2 * g][1], bh[2 * g + 1][0], bh[2 * g + 1][1], pb);
        }
#pragma unroll
        for (int m = 0; m < 2; m++)
#pragma unroll
            for (int n = 0; n < 4; n++) {
                MMA16816(acc[m][n], ah[m], bh[n]);
                MMA16816(acc[m][n], al[m], bh[n]);
            }
        if (t < 7) ST(buf ^ 1, (t + 1) * 16);
        __syncthreads();
    }

#undef LD
#undef ST

    // ---- epilogue: bias + store + optional column stats ----
    float ps[4][2], pq[4][2];
    if (STATS) {
#pragma unroll
        for (int n = 0; n < 4; n++) { ps[n][0] = ps[n][1] = 0.f; pq[n][0] = pq[n][1] = 0.f; }
    }
#pragma unroll
    for (int m = 0; m < 2; m++) {
        int ra = row0 + wm * 32 + m * 16 + (lane >> 2);
        int rb = ra + 8;
        bool vva = ra < NN, vvb = rb < NN;
#pragma unroll
        for (int n = 0; n < 4; n++) {
            int col = wn * 32 + n * 8 + ((lane & 3) << 1);
            float2 b2 = *(const float2*)&bias[col];
            float o0 = acc[m][n][0] + b2.x, o1 = acc[m][n][1] + b2.y;
            float o2 = acc[m][n][2] + b2.x, o3 = acc[m][n][3] + b2.y;
            if (vva) {
                *(float2*)&C[ra * 128 + col] = make_float2(o0, o1);
                if (MIRROR) {
                    __half2 hh = __floats2half2_rn(o0, o1);
                    *(__half2*)&g_Hh[ra * 128 + col] = hh;
                }
            }
            if (vvb) {
                *(float2*)&C[rb * 128 + col] = make_float2(o2, o3);
                if (MIRROR) {
                    __half2 hh = __floats2half2_rn(o2, o3);
                    *(__half2*)&g_Hh[rb * 128 + col] = hh;
                }
            }
            if (STATS) {
                if (vva) { ps[n][0] += o0; pq[n][0] += o0 * o0; ps[n][1] += o1; pq[n][1] += o1 * o1; }
                if (vvb) { ps[n][0] += o2; pq[n][0] += o2 * o2; ps[n][1] += o3; pq[n][1] += o3 * o3; }
            }
        }
    }
    if (STATS) {
        const int contrib = wm * 8 + (lane >> 2);   // 0..15
        __syncthreads();
#pragma unroll
        for (int n = 0; n < 4; n++) {
            int col = wn * 32 + n * 8 + ((lane & 3) << 1);
            red[contrib * 128 + col]     = ps[n][0];
            red[contrib * 128 + col + 1] = ps[n][1];
        }
        __syncthreads();
        if (tid < 128) {
            float s = 0.f;
#pragma unroll
            for (int g = 0; g < 16; g++) s += red[g * 128 + tid];
            atomicAdd(&statOut[tid], s);
        }
        __syncthreads();
#pragma unroll
        for (int n = 0; n < 4; n++) {
            int col = wn * 32 + n * 8 + ((lane & 3) << 1);
            red[contrib * 128 + col]     = pq[n][0];
            red[contrib * 128 + col + 1] = pq[n][1];
        }
        __syncthreads();
        if (tid < 128) {
            float s = 0.f;
#pragma unroll
            for (int g = 0; g < 16; g++) s += red[g * 128 + tid];
            atomicAdd(&statOut[128 + tid], s);
        }
    }
}

// ---------------- stats of A = relu(BN(Y2; st1)) -> statOut ----------------
#define SROWS 256
__global__ void __launch_bounds__(256) k_bnrelu_stats(
    const float* __restrict__ gam, const float* __restrict__ bet,
    const float* __restrict__ statIn, float* __restrict__ statOut)
{
    int tid = threadIdx.x;
    int c4  = tid & 31;
    int rg  = tid >> 5;
    int cc  = c4 * 4;
    float4 s4 = *(const float4*)&statIn[cc];
    float4 q4 = *(const float4*)&statIn[128 + cc];
    float4 m4, r4;
    m4.x = s4.x * (1.0f / NN); r4.x = rsqrtf(q4.x * (1.0f / NN) - m4.x * m4.x + BN_EPS);
    m4.y = s4.y * (1.0f / NN); r4.y = rsqrtf(q4.y * (1.0f / NN) - m4.y * m4.y + BN_EPS);
    m4.z = s4.z * (1.0f / NN); r4.z = rsqrtf(q4.z * (1.0f / NN) - m4.z * m4.z + BN_EPS);
    m4.w = s4.w * (1.0f / NN); r4.w = rsqrtf(q4.w * (1.0f / NN) - m4.w * m4.w + BN_EPS);
    float4 g4 = *(const float4*)&gam[cc];
    float4 b4 = *(const float4*)&bet[cc];
    float s[4] = {0.f, 0.f, 0.f, 0.f}, q[4] = {0.f, 0.f, 0.f, 0.f};
    int rEnd = min(blockIdx.x * SROWS + SROWS, NN);
    for (int r = blockIdx.x * SROWS + rg; r < rEnd; r += 8) {
        float4 v = *(const float4*)&g_Y2[r * 128 + cc];
        float4 a;
        a.x = fmaxf(fmaf(g4.x * (v.x - m4.x), r4.x, b4.x), 0.f);
        a.y = fmaxf(fmaf(g4.y * (v.y - m4.y), r4.y, b4.y), 0.f);
        a.z = fmaxf(fmaf(g4.z * (v.z - m4.z), r4.z, b4.z), 0.f);
        a.w = fmaxf(fmaf(g4.w * (v.w - m4.w), r4.w, b4.w), 0.f);
        s[0] += a.x; q[0] += a.x * a.x;
        s[1] += a.y; q[1] += a.y * a.y;
        s[2] += a.z; q[2] += a.z * a.z;
        s[3] += a.w; q[3] += a.w * a.w;
    }
    __shared__ float shs[8][128];
    __shared__ float shq[8][128];
#pragma unroll
    for (int j = 0; j < 4; j++) { shs[rg][cc + j] = s[j]; shq[rg][cc + j] = q[j]; }
    __syncthreads();
    if (tid < 128) {
        float ts = 0.f, tq = 0.f;
#pragma unroll
        for (int g = 0; g < 8; g++) { ts += shs[g][tid]; tq += shq[g][tid]; }
        atomicAdd(&statOut[tid],       ts);
        atomicAdd(&statOut[128 + tid], tq);
    }
}

// ---------------- Hout = H + relu(BN(relu(BN(Y2; st1)); st2)); optional fp16 mirror ----------------
__global__ void __launch_bounds__(256) k_residual(
    const float* __restrict__ ga, const float* __restrict__ ba,
    const float* __restrict__ gl, const float* __restrict__ bl,
    const float* __restrict__ st1, const float* __restrict__ st2,
    float* __restrict__ out, int writeH)
{
    int i4 = blockIdx.x * blockDim.x + threadIdx.x;
    if (i4 >= NN * 32) return;
    int cc = (i4 & 31) * 4;
    float4 s4 = *(const float4*)&st1[cc];
    float4 q4 = *(const float4*)&st1[128 + cc];
    float4 m1, r1;
    m1.x = s4.x * (1.0f / NN); r1.x = rsqrtf(q4.x * (1.0f / NN) - m1.x * m1.x + BN_EPS);
    m1.y = s4.y * (1.0f / NN); r1.y = rsqrtf(q4.y * (1.0f / NN) - m1.y * m1.y + BN_EPS);
    m1.z = s4.z * (1.0f / NN); r1.z = rsqrtf(q4.z * (1.0f / NN) - m1.z * m1.z + BN_EPS);
    m1.w = s4.w * (1.0f / NN); r1.w = rsqrtf(q4.w * (1.0f / NN) - m1.w * m1.w + BN_EPS);
    float4 ga4 = *(const float4*)&ga[cc];
    float4 ba4 = *(const float4*)&ba[cc];
    float4 t4 = *(const float4*)&st2[cc];
    float4 u4 = *(const float4*)&st2[128 + cc];
    float4 m2, r2;
    m2.x = t4.x * (1.0f / NN); r2.x = rsqrtf(u4.x * (1.0f / NN) - m2.x * m2.x + BN_EPS);
    m2.y = t4.y * (1.0f / NN); r2.y = rsqrtf(u4.y * (1.0f / NN) - m2.y * m2.y + BN_EPS);
    m2.z = t4.z * (1.0f / NN); r2.z = rsqrtf(u4.z * (1.0f / NN) - m2.z * m2.z + BN_EPS);
    m2.w = t4.w * (1.0f / NN); r2.w = rsqrtf(u4.w * (1.0f / NN) - m2.w * m2.w + BN_EPS);
    float4 gl4 = *(const float4*)&gl[cc];
    float4 bl4 = *(const float4*)&bl[cc];

    float4 v = ((const float4*)g_Y2)[i4];
    float4 h = ((const float4*)g_H)[i4];
    float4 a, o;
    a.x = fmaxf(fmaf(ga4.x * (v.x - m1.x), r1.x, ba4.x), 0.f);
    a.y = fmaxf(fmaf(ga4.y * (v.y - m1.y), r1.y, ba4.y), 0.f);
    a.z = fmaxf(fmaf(ga4.z * (v.z - m1.z), r1.z, ba4.z), 0.f);
    a.w = fmaxf(fmaf(ga4.w * (v.w - m1.w), r1.w, ba4.w), 0.f);
    o.x = h.x + fmaxf(fmaf(gl4.x * (a.x - m2.x), r2.x, bl4.x), 0.f);
    o.y = h.y + fmaxf(fmaf(gl4.y * (a.y - m2.y), r2.y, bl4.y), 0.f);
    o.z = h.z + fmaxf(fmaf(gl4.z * (a.z - m2.z), r2.z, bl4.z), 0.f);
    o.w = h.w + fmaxf(fmaf(gl4.w * (a.w - m2.w), r2.w, bl4.w), 0.f);
    ((float4*)out)[i4] = o;
    if (writeH) {
        __half2 h01 = __floats2half2_rn(o.x, o.y);
        __half2 h23 = __floats2half2_rn(o.z, o.w);
        uint2 u;
        u.x = *(uint32_t*)&h01;
        u.y = *(uint32_t*)&h23;
        ((uint2*)g_Hh)[i4] = u;
    }
}

// ---------------- launcher ----------------
extern "C" void kernel_launch(void* const* d_in, const int* in_sizes, int n_in,
                              void* d_out, int out_size)
{
    const float* h       = (const float*)d_in[0];
    const int*   src     = (const int*)  d_in[1];
    const int*   dst     = (const int*)  d_in[2];
    const float* W_embed = (const float*)d_in[3];
    const float* b_embed = (const float*)d_in[4];
    const float* eps     = (const float*)d_in[5];
    const float* W1      = (const float*)d_in[6];
    const float* b1      = (const float*)d_in[7];
    const float* g1      = (const float*)d_in[8];
    const float* be1     = (const float*)d_in[9];
    const float* W2      = (const float*)d_in[10];
    const float* b2      = (const float*)d_in[11];
    const float* ga      = (const float*)d_in[12];
    const float* ba      = (const float*)d_in[13];
    const float* gl      = (const float*)d_in[14];
    const float* bl      = (const float*)d_in[15];

    float *pH, *pX, *pY1, *pY2, *pStats;
    cudaGetSymbolAddress((void**)&pH,     g_H);
    cudaGetSymbolAddress((void**)&pX,     g_X);
    cudaGetSymbolAddress((void**)&pY1,    g_Y1);
    cudaGetSymbolAddress((void**)&pY2,    g_Y2);
    cudaGetSymbolAddress((void**)&pStats, g_statsAll);
    __half* pWf;
    cudaGetSymbolAddress((void**)&pWf, g_Wf);

    const int GEMM_GRID = (NN + GBM - 1) / GBM;      // 782
    const int EW_GRID   = (NN * 32) / 256;           // 6250
    const int ST_GRID   = (NN + SROWS - 1) / SROWS;  // 196

    // launch order keeps the embedding GEMM at index 3 (ncu profiles it)
    k_zero_all<<<(NN + 255) / 256, 256>>>();                         // 0
    k_hist<<<(NE + 255) / 256, 256>>>(dst);                          // 1
    k_prepW<<<dim3(64, 9), 256>>>(W_embed, W1, W2);                  // 2
    k_hgemm<false, false, true><<<GEMM_GRID, 256>>>(                 // 3 <- profiled
        h, pWf, b_embed, nullptr, nullptr, nullptr, nullptr, pH);
    k_scan1<<<SCAN_BLKS, 256>>>();                                   // 4
    k_scan23<<<SCAN_BLKS, 256>>>();                                  // 5
    k_fill<<<(NE + 255) / 256, 256>>>(src, dst);                     // 6

    for (int i = 0; i < LL; i++) {
        float* st0 = pStats + (i * 3 + 0) * 2 * D;
        float* st1 = pStats + (i * 3 + 1) * 2 * D;
        float* st2 = pStats + (i * 3 + 2) * 2 * D;

        k_agg<<<EW_GRID, 256>>>(eps, i);
        k_hgemm<false, true, false><<<GEMM_GRID, 256>>>(
            pX, pWf + (1 + i) * 16384, b1 + i * D,
            nullptr, nullptr, nullptr, st0, pY1);
        k_hgemm<true, true, false><<<GEMM_GRID, 256>>>(
            pY1, pWf + (5 + i) * 16384, b2 + i * D,
            g1 + i * D, be1 + i * D, st0, st1, pY2);
        k_bnrelu_stats<<<ST_GRID, 256>>>(ga + i * D, ba + i * D, st1, st2);
        float* out = (i == LL - 1) ? (float*)d_out : pH;
        k_residual<<<EW_GRID, 256>>>(ga + i * D, ba + i * D, gl + i * D, bl + i * D,
                                     st1, st2, out, (i == LL - 1) ? 0 : 1);
    }
}